// round 3
// baseline (speedup 1.0000x reference)
#include <cuda_runtime.h>

namespace {
constexpr int NX = 256, NY = 256, NZ = 128;
constexpr int NZ4 = NZ / 4;            // 32 float4 per z-line
constexpr int XS4 = NY * NZ4;          // 8192 float4 per x-plane per field
constexpr int FS4 = NX * XS4;          // float4 per field
constexpr int TX  = 16;                // x-planes marched per block
constexpr int BY  = 8;                 // y rows per block

constexpr float CVc = 717.0f;
constexpr float MUc = 1.8e-5f, KTHc = 0.025f, Gc = 9.8f;
constexpr float Rg  = 287.0f;

constexpr double DXd = 1.0 / NX, DYd = 1.0 / NY, DZd = 1.0 / (NZ - 1);
constexpr float inv2dx = (float)(0.5 / DXd);
constexpr float inv2dy = (float)(0.5 / DYd);
constexpr float inv2dz = (float)(0.5 / DZd);
constexpr float invdx2 = (float)(1.0 / (DXd * DXd));
constexpr float invdy2 = (float)(1.0 / (DYd * DYd));
constexpr float invdz2 = (float)(1.0 / (DZd * DZd));
constexpr float kTco   = KTHc / CVc;

__device__ __forceinline__ float4 operator+(float4 a, float4 b){ return make_float4(a.x+b.x, a.y+b.y, a.z+b.z, a.w+b.w); }
__device__ __forceinline__ float4 operator-(float4 a, float4 b){ return make_float4(a.x-b.x, a.y-b.y, a.z-b.z, a.w-b.w); }
__device__ __forceinline__ float4 operator*(float4 a, float4 b){ return make_float4(a.x*b.x, a.y*b.y, a.z*b.z, a.w*b.w); }
__device__ __forceinline__ float4 operator*(float4 a, float s){ return make_float4(a.x*s, a.y*s, a.z*s, a.w*s); }
__device__ __forceinline__ float4 operator*(float s, float4 a){ return a * s; }

__device__ __forceinline__ float4 zm_of(float4 a){
    float p = __shfl_up_sync(0xffffffffu, a.w, 1);
    return make_float4(p, a.x, a.y, a.z);
}
__device__ __forceinline__ float4 zp_of(float4 a){
    float n = __shfl_down_sync(0xffffffffu, a.x, 1);
    return make_float4(a.y, a.z, a.w, n);
}

__device__ __forceinline__ int gidx(int f, int x, int y, int lane){
    return f * FS4 + x * XS4 + y * NZ4 + lane;
}
__device__ __forceinline__ int sidx(int buf, int f, int r, int lane){
    return ((buf * 6 + f) * 10 + r) * 32 + lane;
}

__global__ __launch_bounds__(256, 2)
void rb_march(const float4* __restrict__ s, float4* __restrict__ o)
{
    extern __shared__ float4 sm[];     // [2][6][10 rows][32 lanes]

    const int lane = threadIdx.x;      // z chunk (4 z per lane)
    const int ty   = threadIdx.y;      // 0..7
    const int y0   = blockIdx.x * BY;
    const int y    = y0 + ty;
    const int x0   = blockIdx.y * TX;
    const int ymr  = (y0 - 1) & (NY - 1);
    const int ypr  = (y0 + BY) & (NY - 1);
    const int row  = ty + 1;
    const bool haloLo = (ty == 0);
    const bool haloHi = (ty == BY - 1);

    const float4 m = make_float4(lane == 0 ? 0.0f : 1.0f, 1.0f, 1.0f, lane == 31 ? 0.0f : 1.0f);

    float4 pm[6], pc[6];
    {
        const int xm1 = (x0 - 1) & (NX - 1);
        #pragma unroll
        for (int f = 0; f < 6; f++) pm[f] = s[gidx(f, xm1, y, lane)];
        #pragma unroll
        for (int f = 0; f < 6; f++) { pc[f] = s[gidx(f, x0, y, lane)]; sm[sidx(0, f, row, lane)] = pc[f]; }
        if (haloLo) {
            #pragma unroll
            for (int f = 0; f < 6; f++) sm[sidx(0, f, 0, lane)] = s[gidx(f, x0, ymr, lane)];
        }
        if (haloHi) {
            #pragma unroll
            for (int f = 0; f < 6; f++) sm[sidx(0, f, 9, lane)] = s[gidx(f, x0, ypr, lane)];
        }
    }
    __syncthreads();

    int cur = 0;
    #pragma unroll 1
    for (int xi = 0; xi < TX; xi++) {
        const int x   = x0 + xi;
        const int xn  = (x + 1) & (NX - 1);
        const int nxt = cur ^ 1;

        // --- issue loads for plane x+1 (independent of compute below) ---
        float4 pn[6];
        #pragma unroll
        for (int f = 0; f < 6; f++) pn[f] = s[gidx(f, xn, y, lane)];
        float4 hn0, hn1, hn2, hn3, hn4, hn5;
        if (haloLo) {
            hn0 = s[gidx(0, xn, ymr, lane)]; hn1 = s[gidx(1, xn, ymr, lane)];
            hn2 = s[gidx(2, xn, ymr, lane)]; hn3 = s[gidx(3, xn, ymr, lane)];
            hn4 = s[gidx(4, xn, ymr, lane)]; hn5 = s[gidx(5, xn, ymr, lane)];
        }
        if (haloHi) {
            hn0 = s[gidx(0, xn, ypr, lane)]; hn1 = s[gidx(1, xn, ypr, lane)];
            hn2 = s[gidx(2, xn, ypr, lane)]; hn3 = s[gidx(3, xn, ypr, lane)];
            hn4 = s[gidx(4, xn, ypr, lane)]; hn5 = s[gidx(5, xn, ypr, lane)];
        }

        // --- compute plane x ---
        const float4 uc = pc[0], vc = pc[1], wc = pc[2], rc = pc[3], Tc = pc[4], ccv = pc[5];
        const float4 rinv = make_float4(1.0f / rc.x, 1.0f / rc.y, 1.0f / rc.z, 1.0f / rc.w);

        // rho & T (pressure, dT, drou)
        {
            const float4 rym = sm[sidx(cur, 3, row - 1, lane)], ryp = sm[sidx(cur, 3, row + 1, lane)];
            const float4 Tym = sm[sidx(cur, 4, row - 1, lane)], Typ = sm[sidx(cur, 4, row + 1, lane)];
            const float4 rzm = zm_of(rc), rzp = zp_of(rc);
            const float4 Tzm = zm_of(Tc), Tzp = zp_of(Tc);

            const float4 dpdy = (ryp * Typ - rym * Tym) * (Rg * inv2dy);
            const float4 dpdz = (rzp * Tzp - rzm * Tzm) * (Rg * inv2dz);
            const float4 dpdx = (pn[3] * pn[4] - pm[3] * pm[4]) * (Rg * inv2dx);

            // dT
            const float4 lapT = (pn[4] + pm[4] - Tc * 2.0f) * invdx2 + (Typ + Tym - Tc * 2.0f) * invdy2 + (Tzp + Tzm - Tc * 2.0f) * invdz2;
            const float4 advT = uc * ((pn[4] - pm[4]) * inv2dx) + vc * ((Typ - Tym) * inv2dy) + wc * ((Tzp - Tzm) * inv2dz);
            o[gidx(4, x, y, lane)] = ((lapT * kTco) * rinv - advT) * m;

            // drou
            o[gidx(3, x, y, lane)] = (pm[3] * pm[0] - pn[3] * pn[0]) * inv2dx;

            // u
            {
                const float4 uym = sm[sidx(cur, 0, row - 1, lane)], uyp = sm[sidx(cur, 0, row + 1, lane)];
                const float4 uzm = zm_of(uc), uzp = zp_of(uc);
                const float4 lapU = (pn[0] + pm[0] - uc * 2.0f) * invdx2 + (uyp + uym - uc * 2.0f) * invdy2 + (uzp + uzm - uc * 2.0f) * invdz2;
                const float4 advU = uc * ((pn[0] - pm[0]) * inv2dx) + vc * ((uyp - uym) * inv2dy) + wc * ((uzp - uzm) * inv2dz);
                o[gidx(0, x, y, lane)] = ((lapU * MUc - dpdx) * rinv - advU) * m;
            }
            // v
            {
                const float4 vym = sm[sidx(cur, 1, row - 1, lane)], vyp = sm[sidx(cur, 1, row + 1, lane)];
                const float4 vzm = zm_of(vc), vzp = zp_of(vc);
                const float4 lapV = (pn[1] + pm[1] - vc * 2.0f) * invdx2 + (vyp + vym - vc * 2.0f) * invdy2 + (vzp + vzm - vc * 2.0f) * invdz2;
                const float4 advV = uc * ((pn[1] - pm[1]) * inv2dx) + vc * ((vyp - vym) * inv2dy) + wc * ((vzp - vzm) * inv2dz);
                o[gidx(1, x, y, lane)] = ((lapV * MUc - dpdy) * rinv - advV) * m;
            }
            // w  ((-G*rho)/rho = -G)
            {
                const float4 wym = sm[sidx(cur, 2, row - 1, lane)], wyp = sm[sidx(cur, 2, row + 1, lane)];
                const float4 wzm = zm_of(wc), wzp = zp_of(wc);
                const float4 lapW = (pn[2] + pm[2] - wc * 2.0f) * invdx2 + (wyp + wym - wc * 2.0f) * invdy2 + (wzp + wzm - wc * 2.0f) * invdz2;
                const float4 advW = uc * ((pn[2] - pm[2]) * inv2dx) + vc * ((wyp - wym) * inv2dy) + wc * ((wzp - wzm) * inv2dz);
                float4 dw = (lapW * MUc - dpdz) * rinv - advW;
                dw = make_float4(dw.x - Gc, dw.y - Gc, dw.z - Gc, dw.w - Gc);
                o[gidx(2, x, y, lane)] = dw * m;
            }
            // c  (one-sided z at walls, NOT masked)
            {
                const float4 cym = sm[sidx(cur, 5, row - 1, lane)], cyp = sm[sidx(cur, 5, row + 1, lane)];
                const float4 czm = zm_of(ccv), czp = zp_of(ccv);
                float4 dcdz = (czp - czm) * inv2dz;
                if (lane == 0)  dcdz.x = (-3.0f * ccv.x + 4.0f * ccv.y - ccv.z) * inv2dz;
                if (lane == 31) dcdz.w = ( 3.0f * ccv.w - 4.0f * ccv.z + ccv.y) * inv2dz;
                const float4 advC = uc * ((pn[5] - pm[5]) * inv2dx) + vc * ((cyp - cym) * inv2dy) + wc * dcdz;
                o[gidx(5, x, y, lane)] = make_float4(-advC.x, -advC.y, -advC.z, -advC.w);
            }
        }

        // --- publish plane x+1 to the other smem buffer ---
        #pragma unroll
        for (int f = 0; f < 6; f++) sm[sidx(nxt, f, row, lane)] = pn[f];
        if (haloLo) {
            sm[sidx(nxt, 0, 0, lane)] = hn0; sm[sidx(nxt, 1, 0, lane)] = hn1;
            sm[sidx(nxt, 2, 0, lane)] = hn2; sm[sidx(nxt, 3, 0, lane)] = hn3;
            sm[sidx(nxt, 4, 0, lane)] = hn4; sm[sidx(nxt, 5, 0, lane)] = hn5;
        }
        if (haloHi) {
            sm[sidx(nxt, 0, 9, lane)] = hn0; sm[sidx(nxt, 1, 9, lane)] = hn1;
            sm[sidx(nxt, 2, 9, lane)] = hn2; sm[sidx(nxt, 3, 9, lane)] = hn3;
            sm[sidx(nxt, 4, 9, lane)] = hn4; sm[sidx(nxt, 5, 9, lane)] = hn5;
        }
        __syncthreads();

        #pragma unroll
        for (int f = 0; f < 6; f++) { pm[f] = pc[f]; pc[f] = pn[f]; }
        cur = nxt;
    }
}
} // namespace

extern "C" void kernel_launch(void* const* d_in, const int* in_sizes, int n_in,
                              void* d_out, int out_size)
{
    const float4* s = (const float4*)d_in[0];
    float4* o = (float4*)d_out;
    constexpr int SMEM = 2 * 6 * 10 * 32 * (int)sizeof(float4);  // 61440 B
    static bool attrSet = false;
    if (!attrSet) {
        cudaFuncSetAttribute(rb_march, cudaFuncAttributeMaxDynamicSharedMemorySize, SMEM);
        attrSet = true;
    }
    dim3 block(32, BY, 1);                  // 256 threads
    dim3 grid(NY / BY, NX / TX, 1);         // 32 x 16 = 512 blocks
    rb_march<<<grid, block, SMEM>>>(s, o);
}

// round 4
// speedup vs baseline: 1.1212x; 1.1212x over previous
#include <cuda_runtime.h>

namespace {
constexpr int NX = 256, NY = 256, NZ = 128;
constexpr int NZ4 = NZ / 4, XS4 = NY * NZ4, FS4 = NX * XS4;

constexpr float CVc = 717.0f;
constexpr float MUc = 1.8e-5f, KTHc = 0.025f, Gc = 9.8f;
constexpr float Rg  = 287.0f;

constexpr double DXd = 1.0 / NX, DYd = 1.0 / NY, DZd = 1.0 / (NZ - 1);
constexpr float inv2dx = (float)(0.5 / DXd);
constexpr float inv2dy = (float)(0.5 / DYd);
constexpr float inv2dz = (float)(0.5 / DZd);
constexpr float invdx2 = (float)(1.0 / (DXd * DXd));
constexpr float invdy2 = (float)(1.0 / (DYd * DYd));
constexpr float invdz2 = (float)(1.0 / (DZd * DZd));
constexpr float kTco   = KTHc / CVc;

__device__ __forceinline__ float4 operator+(float4 a, float4 b){ return make_float4(a.x+b.x, a.y+b.y, a.z+b.z, a.w+b.w); }
__device__ __forceinline__ float4 operator-(float4 a, float4 b){ return make_float4(a.x-b.x, a.y-b.y, a.z-b.z, a.w-b.w); }
__device__ __forceinline__ float4 operator*(float4 a, float4 b){ return make_float4(a.x*b.x, a.y*b.y, a.z*b.z, a.w*b.w); }
__device__ __forceinline__ float4 operator*(float4 a, float s){ return make_float4(a.x*s, a.y*s, a.z*s, a.w*s); }
__device__ __forceinline__ float4 operator*(float s, float4 a){ return a * s; }

__device__ __forceinline__ float4 zm_of(float4 a){
    float p = __shfl_up_sync(0xffffffffu, a.w, 1);
    return make_float4(p, a.x, a.y, a.z);
}
__device__ __forceinline__ float4 zp_of(float4 a){
    float n = __shfl_down_sync(0xffffffffu, a.x, 1);
    return make_float4(a.y, a.z, a.w, n);
}

__device__ __forceinline__ float4 maskwall(float4 v, bool lo, bool hi){
    if (lo) v.x = 0.0f;
    if (hi) v.w = 0.0f;
    return v;
}

__global__ __launch_bounds__(256, 3)
void rb4_kernel(const float4* __restrict__ s, float4* __restrict__ o)
{
    const int lane = threadIdx.x;                       // z chunk (4 z per lane)
    const int y = (blockIdx.x << 3) | threadIdx.y;      // 8 y per block
    const int x = blockIdx.y;

    const int rowc = y * NZ4 + lane;
    const int ic  = x * XS4 + rowc;
    const int ixm = ((x + NX - 1) & (NX - 1)) * XS4 + rowc;
    const int ixp = ((x + 1)      & (NX - 1)) * XS4 + rowc;
    const int iym = x * XS4 + ((y + NY - 1) & (NY - 1)) * NZ4 + lane;
    const int iyp = x * XS4 + ((y + 1)      & (NY - 1)) * NZ4 + lane;

    const bool lo = (lane == 0);
    const bool hi = (lane == 31);

    // centers
    const float4 uc = s[0 * FS4 + ic];
    const float4 vc = s[1 * FS4 + ic];
    const float4 wc = s[2 * FS4 + ic];
    const float4 rc = s[3 * FS4 + ic];
    const float4 rinv = make_float4(1.0f / rc.x, 1.0f / rc.y, 1.0f / rc.z, 1.0f / rc.w);

    // ---- phase 1: rho & T → dT, pressure gradients (keep rxm/rxp for drou) ----
    const float4 rxm = s[3 * FS4 + ixm], rxp = s[3 * FS4 + ixp];
    float4 dpdx, dpdy, dpdz;
    {
        const float4 rym = s[3 * FS4 + iym], ryp = s[3 * FS4 + iyp];
        const float4 Tc  = s[4 * FS4 + ic];
        const float4 Txm = s[4 * FS4 + ixm], Txp = s[4 * FS4 + ixp];
        const float4 Tym = s[4 * FS4 + iym], Typ = s[4 * FS4 + iyp];
        const float4 rzm = zm_of(rc), rzp = zp_of(rc);
        const float4 Tzm = zm_of(Tc), Tzp = zp_of(Tc);

        dpdx = (rxp * Txp - rxm * Txm) * (Rg * inv2dx);
        dpdy = (ryp * Typ - rym * Tym) * (Rg * inv2dy);
        dpdz = (rzp * Tzp - rzm * Tzm) * (Rg * inv2dz);

        const float4 lapT = (Txp + Txm - Tc * 2.0f) * invdx2 + (Typ + Tym - Tc * 2.0f) * invdy2 + (Tzp + Tzm - Tc * 2.0f) * invdz2;
        const float4 advT = uc * ((Txp - Txm) * inv2dx) + vc * ((Typ - Tym) * inv2dy) + wc * ((Tzp - Tzm) * inv2dz);
        __stcs(&o[4 * FS4 + ic], maskwall((lapT * kTco) * rinv - advT, lo, hi));
    }

    // ---- phase 2: u (+ drou) ----
    {
        const float4 uxm = s[0 * FS4 + ixm], uxp = s[0 * FS4 + ixp];
        const float4 uym = s[0 * FS4 + iym], uyp = s[0 * FS4 + iyp];
        const float4 uzm = zm_of(uc), uzp = zp_of(uc);

        __stcs(&o[3 * FS4 + ic], (rxm * uxm - rxp * uxp) * inv2dx);

        const float4 lapU = (uxp + uxm - uc * 2.0f) * invdx2 + (uyp + uym - uc * 2.0f) * invdy2 + (uzp + uzm - uc * 2.0f) * invdz2;
        const float4 advU = uc * ((uxp - uxm) * inv2dx) + vc * ((uyp - uym) * inv2dy) + wc * ((uzp - uzm) * inv2dz);
        __stcs(&o[0 * FS4 + ic], maskwall((lapU * MUc - dpdx) * rinv - advU, lo, hi));
    }

    // ---- phase 3: v ----
    {
        const float4 vxm = s[1 * FS4 + ixm], vxp = s[1 * FS4 + ixp];
        const float4 vym = s[1 * FS4 + iym], vyp = s[1 * FS4 + iyp];
        const float4 vzm = zm_of(vc), vzp = zp_of(vc);
        const float4 lapV = (vxp + vxm - vc * 2.0f) * invdx2 + (vyp + vym - vc * 2.0f) * invdy2 + (vzp + vzm - vc * 2.0f) * invdz2;
        const float4 advV = uc * ((vxp - vxm) * inv2dx) + vc * ((vyp - vym) * inv2dy) + wc * ((vzp - vzm) * inv2dz);
        __stcs(&o[1 * FS4 + ic], maskwall((lapV * MUc - dpdy) * rinv - advV, lo, hi));
    }

    // ---- phase 4: w  ((-G*rho)/rho == -G) ----
    {
        const float4 wxm = s[2 * FS4 + ixm], wxp = s[2 * FS4 + ixp];
        const float4 wym = s[2 * FS4 + iym], wyp = s[2 * FS4 + iyp];
        const float4 wzm = zm_of(wc), wzp = zp_of(wc);
        const float4 lapW = (wxp + wxm - wc * 2.0f) * invdx2 + (wyp + wym - wc * 2.0f) * invdy2 + (wzp + wzm - wc * 2.0f) * invdz2;
        const float4 advW = uc * ((wxp - wxm) * inv2dx) + vc * ((wyp - wym) * inv2dy) + wc * ((wzp - wzm) * inv2dz);
        float4 dw = (lapW * MUc - dpdz) * rinv - advW;
        dw = make_float4(dw.x - Gc, dw.y - Gc, dw.z - Gc, dw.w - Gc);
        __stcs(&o[2 * FS4 + ic], maskwall(dw, lo, hi));
    }

    // ---- phase 5: c (one-sided z at walls, NOT masked) ----
    {
        const float4 cc  = s[5 * FS4 + ic];
        const float4 cxm = s[5 * FS4 + ixm], cxp = s[5 * FS4 + ixp];
        const float4 cym = s[5 * FS4 + iym], cyp = s[5 * FS4 + iyp];
        const float4 czm = zm_of(cc), czp = zp_of(cc);

        float4 dcdz = (czp - czm) * inv2dz;
        if (lo) dcdz.x = (-3.0f * cc.x + 4.0f * cc.y - cc.z) * inv2dz;
        if (hi) dcdz.w = ( 3.0f * cc.w - 4.0f * cc.z + cc.y) * inv2dz;

        const float4 advC = uc * ((cxp - cxm) * inv2dx) + vc * ((cyp - cym) * inv2dy) + wc * dcdz;
        __stcs(&o[5 * FS4 + ic], make_float4(-advC.x, -advC.y, -advC.z, -advC.w));
    }
}
} // namespace

extern "C" void kernel_launch(void* const* d_in, const int* in_sizes, int n_in,
                              void* d_out, int out_size)
{
    const float4* s = (const float4*)d_in[0];
    float4* o = (float4*)d_out;
    dim3 block(32, 8, 1);             // 256 threads: 32 z-chunks × 8 y
    dim3 grid(NY / 8, NX, 1);         // 32 × 256 blocks
    rb4_kernel<<<grid, block>>>(s, o);
}